// round 1
// baseline (speedup 1.0000x reference)
#include <cuda_runtime.h>
#include <math.h>

// Problem constants (hard-coded for MultiHeadAttention_82824149336918)
#define Bz  2
#define Sq  2048
#define Dm  1024
#define Hn  16
#define DHd 64
#define BH  (Bz * Hn)   // 32

// ---------------------------------------------------------------------------
// Scratch (allocation-free: __device__ globals). 16 MB each, 64 MB total.
// ---------------------------------------------------------------------------
__device__ float g_q[(size_t)BH * Sq * DHd];
__device__ float g_k[(size_t)BH * Sq * DHd];
__device__ float g_v[(size_t)BH * Sq * DHd];
__device__ float g_ctx[(size_t)Bz * Sq * Dm];
__device__ int   g_mask_is_int;

// ---------------------------------------------------------------------------
// Mask dtype detector. Reads ONLY the first Bz*Sq = 4096 bytes (safe whether
// the mask is bool (4096 B) or int32 (16384 B)). int32 0/1 values have all
// bytes at offset %4 != 0 equal to zero; random bool bytes do not.
// Deterministic in the input -> graph-replay safe.
// ---------------------------------------------------------------------------
__global__ void detect_mask_kernel(const unsigned char* __restrict__ m) {
    __shared__ int any;
    if (threadIdx.x == 0) any = 0;
    __syncthreads();
    int local = 0;
    for (int i = threadIdx.x; i < Bz * Sq; i += blockDim.x)
        if ((i & 3) && m[i]) local = 1;
    if (local) atomicOr(&any, 1);
    __syncthreads();
    if (threadIdx.x == 0) g_mask_is_int = (any == 0) ? 1 : 0;
}

// ---------------------------------------------------------------------------
// 128x128x8 fp32 SGEMM, 256 threads, 8x8 per thread. C = A*W + bias.
// headsplit=1 remaps output j = h*64+dh, i = b*S+s into [BH,S,DH] scratch.
// ---------------------------------------------------------------------------
__global__ void __launch_bounds__(256) sgemm128(
    const float* __restrict__ A, const float* __restrict__ W,
    const float* __restrict__ bias, float* __restrict__ C,
    int M, int N, int K, int headsplit)
{
    __shared__ float As[8][128];
    __shared__ float Bs[8][128];
    const int tid = threadIdx.x;
    const int bm = blockIdx.y * 128;
    const int bn = blockIdx.x * 128;
    const int tx = tid & 15;      // n direction
    const int ty = tid >> 4;      // m direction

    float acc[8][8];
#pragma unroll
    for (int i = 0; i < 8; i++)
#pragma unroll
        for (int j = 0; j < 8; j++) acc[i][j] = 0.f;

    const int am  = tid >> 1;            // A tile row (0..127)
    const int akq = (tid & 1) * 4;       // A tile k quad
    const int bk  = tid >> 5;            // B tile k row (0..7)
    const int bn4 = (tid & 31) * 4;      // B tile n quad

    for (int k0 = 0; k0 < K; k0 += 8) {
        float4 a4 = *(const float4*)(A + (size_t)(bm + am) * K + k0 + akq);
        As[akq + 0][am] = a4.x; As[akq + 1][am] = a4.y;
        As[akq + 2][am] = a4.z; As[akq + 3][am] = a4.w;
        *(float4*)&Bs[bk][bn4] =
            *(const float4*)(W + (size_t)(k0 + bk) * N + bn + bn4);
        __syncthreads();
#pragma unroll
        for (int kk = 0; kk < 8; kk++) {
            float a[8], b[8];
            *(float4*)(a)     = *(float4*)&As[kk][ty * 8];
            *(float4*)(a + 4) = *(float4*)&As[kk][ty * 8 + 4];
            *(float4*)(b)     = *(float4*)&Bs[kk][tx * 8];
            *(float4*)(b + 4) = *(float4*)&Bs[kk][tx * 8 + 4];
#pragma unroll
            for (int i = 0; i < 8; i++)
#pragma unroll
                for (int j = 0; j < 8; j++)
                    acc[i][j] += a[i] * b[j];
        }
        __syncthreads();
    }

#pragma unroll
    for (int i = 0; i < 8; i++) {
        const int gi = bm + ty * 8 + i;
#pragma unroll
        for (int j = 0; j < 8; j++) {
            const int gj = bn + tx * 8 + j;
            const float val = acc[i][j] + bias[gj];
            if (!headsplit) {
                C[(size_t)gi * N + gj] = val;
            } else {
                const int bb = gi >> 11;        // / Sq
                const int ss = gi & (Sq - 1);
                const int hh = gj >> 6;         // / DHd
                const int dh = gj & (DHd - 1);
                C[(((size_t)(bb * Hn + hh)) * Sq + ss) * DHd + dh] = val;
            }
        }
    }
}

// ---------------------------------------------------------------------------
// scores[bh, qi, kj] = (q . k) / 8, masked -> -inf. 128x128 tile per block,
// K-dim = 64. Writes raw (pre-softmax) scores into the attn region of d_out.
// ---------------------------------------------------------------------------
__global__ void __launch_bounds__(256) scores_kernel(
    const void* __restrict__ mask, float* __restrict__ attn)
{
    const int bh = blockIdx.z;
    const int b  = bh / Hn;
    const float* q = g_q + (size_t)bh * Sq * DHd;
    const float* k = g_k + (size_t)bh * Sq * DHd;

    __shared__ float Qs[8][128];
    __shared__ float Ks[8][128];
    const int tid = threadIdx.x;
    const int bm = blockIdx.y * 128;   // query rows
    const int bn = blockIdx.x * 128;   // key rows
    const int tx = tid & 15, ty = tid >> 4;

    float acc[8][8];
#pragma unroll
    for (int i = 0; i < 8; i++)
#pragma unroll
        for (int j = 0; j < 8; j++) acc[i][j] = 0.f;

    const int am  = tid >> 1;
    const int akq = (tid & 1) * 4;

    for (int k0 = 0; k0 < DHd; k0 += 8) {
        float4 a4 = *(const float4*)(q + (size_t)(bm + am) * DHd + k0 + akq);
        Qs[akq + 0][am] = a4.x; Qs[akq + 1][am] = a4.y;
        Qs[akq + 2][am] = a4.z; Qs[akq + 3][am] = a4.w;
        float4 b4 = *(const float4*)(k + (size_t)(bn + am) * DHd + k0 + akq);
        Ks[akq + 0][am] = b4.x; Ks[akq + 1][am] = b4.y;
        Ks[akq + 2][am] = b4.z; Ks[akq + 3][am] = b4.w;
        __syncthreads();
#pragma unroll
        for (int kk = 0; kk < 8; kk++) {
            float a[8], bb[8];
            *(float4*)(a)      = *(float4*)&Qs[kk][ty * 8];
            *(float4*)(a + 4)  = *(float4*)&Qs[kk][ty * 8 + 4];
            *(float4*)(bb)     = *(float4*)&Ks[kk][tx * 8];
            *(float4*)(bb + 4) = *(float4*)&Ks[kk][tx * 8 + 4];
#pragma unroll
            for (int i = 0; i < 8; i++)
#pragma unroll
                for (int j = 0; j < 8; j++)
                    acc[i][j] += a[i] * bb[j];
        }
        __syncthreads();
    }

    const int mint = g_mask_is_int;
    const float NEG_INF = -__int_as_float(0x7f800000);
#pragma unroll
    for (int i = 0; i < 8; i++) {
        const int gi = bm + ty * 8 + i;
        float* row = attn + ((size_t)bh * Sq + gi) * Sq;
#pragma unroll
        for (int j = 0; j < 8; j++) {
            const int gj = bn + tx * 8 + j;
            bool mv;
            if (mint) mv = ((const int*)mask)[b * Sq + gj] != 0;
            else      mv = ((const unsigned char*)mask)[b * Sq + gj] != 0;
            row[gj] = mv ? acc[i][j] * 0.125f : NEG_INF;
        }
    }
}

// ---------------------------------------------------------------------------
// In-place row softmax over S=2048. One block (256 threads) per row; each
// thread holds its 8 values in registers -> single read, single write.
// ---------------------------------------------------------------------------
__global__ void __launch_bounds__(256) softmax_kernel(float* __restrict__ attn)
{
    const size_t row = blockIdx.x;
    float4* p = (float4*)(attn + row * Sq);
    const int tid = threadIdx.x;

    float4 v0 = p[tid];
    float4 v1 = p[tid + 256];

    float m = fmaxf(fmaxf(fmaxf(v0.x, v0.y), fmaxf(v0.z, v0.w)),
                    fmaxf(fmaxf(v1.x, v1.y), fmaxf(v1.z, v1.w)));
#pragma unroll
    for (int o = 16; o; o >>= 1) m = fmaxf(m, __shfl_xor_sync(~0u, m, o));

    __shared__ float sred[8];
    if ((tid & 31) == 0) sred[tid >> 5] = m;
    __syncthreads();
    if (tid < 32) {
        float t = (tid < 8) ? sred[tid] : -__int_as_float(0x7f800000);
#pragma unroll
        for (int o = 4; o; o >>= 1) t = fmaxf(t, __shfl_xor_sync(~0u, t, o));
        if (tid == 0) sred[0] = t;
    }
    __syncthreads();
    m = sred[0];
    __syncthreads();   // protect sred before sum reuse

    float e[8];
    e[0] = expf(v0.x - m); e[1] = expf(v0.y - m);
    e[2] = expf(v0.z - m); e[3] = expf(v0.w - m);
    e[4] = expf(v1.x - m); e[5] = expf(v1.y - m);
    e[6] = expf(v1.z - m); e[7] = expf(v1.w - m);
    float s = e[0] + e[1] + e[2] + e[3] + e[4] + e[5] + e[6] + e[7];
#pragma unroll
    for (int o = 16; o; o >>= 1) s += __shfl_xor_sync(~0u, s, o);
    if ((tid & 31) == 0) sred[tid >> 5] = s;
    __syncthreads();
    if (tid < 32) {
        float t = (tid < 8) ? sred[tid] : 0.f;
#pragma unroll
        for (int o = 4; o; o >>= 1) t += __shfl_xor_sync(~0u, t, o);
        if (tid == 0) sred[0] = t;
    }
    __syncthreads();
    const float inv = 1.f / sred[0];

    v0 = make_float4(e[0] * inv, e[1] * inv, e[2] * inv, e[3] * inv);
    v1 = make_float4(e[4] * inv, e[5] * inv, e[6] * inv, e[7] * inv);
    p[tid]       = v0;
    p[tid + 256] = v1;
}

// ---------------------------------------------------------------------------
// ctx = attn @ V per (b,h). Tile 128(M) x 64(N), K-step 16. Writes directly
// in [B,S,D] layout (col = h*64 + n) for the output projection GEMM.
// ---------------------------------------------------------------------------
__global__ void __launch_bounds__(256) ctx_kernel(
    const float* __restrict__ attn, float* __restrict__ ctx)
{
    const int bh = blockIdx.z;
    const int b = bh / Hn, h = bh % Hn;
    const float* P = attn + (size_t)bh * Sq * Sq;
    const float* V = g_v  + (size_t)bh * Sq * DHd;
    const int bm = blockIdx.y * 128;

    __shared__ float Ps[16][128];
    __shared__ float Vs[16][64];
    const int tid = threadIdx.x;
    const int tx = tid & 15;    // n dir (4 cols)
    const int ty = tid >> 4;    // m dir (8 rows)

    float acc[8][4];
#pragma unroll
    for (int i = 0; i < 8; i++)
#pragma unroll
        for (int j = 0; j < 4; j++) acc[i][j] = 0.f;

    for (int k0 = 0; k0 < Sq; k0 += 16) {
#pragma unroll
        for (int l = 0; l < 2; l++) {
            const int idx = tid + l * 256;
            const int m = idx >> 2, kq = (idx & 3) * 4;
            float4 a = *(const float4*)(P + (size_t)(bm + m) * Sq + k0 + kq);
            Ps[kq + 0][m] = a.x; Ps[kq + 1][m] = a.y;
            Ps[kq + 2][m] = a.z; Ps[kq + 3][m] = a.w;
        }
        {
            const int kk = tid >> 4, n4 = (tid & 15) * 4;
            *(float4*)&Vs[kk][n4] =
                *(const float4*)(V + (size_t)(k0 + kk) * DHd + n4);
        }
        __syncthreads();
#pragma unroll
        for (int kk = 0; kk < 16; kk++) {
            float a[8], bb[4];
            *(float4*)(a)     = *(float4*)&Ps[kk][ty * 8];
            *(float4*)(a + 4) = *(float4*)&Ps[kk][ty * 8 + 4];
            *(float4*)(bb)    = *(float4*)&Vs[kk][tx * 4];
#pragma unroll
            for (int i = 0; i < 8; i++)
#pragma unroll
                for (int j = 0; j < 4; j++)
                    acc[i][j] += a[i] * bb[j];
        }
        __syncthreads();
    }

#pragma unroll
    for (int i = 0; i < 8; i++) {
        const size_t off =
            ((size_t)b * Sq + bm + ty * 8 + i) * Dm + h * DHd + tx * 4;
        *(float4*)&ctx[off] =
            make_float4(acc[i][0], acc[i][1], acc[i][2], acc[i][3]);
    }
}

// ---------------------------------------------------------------------------
// Launch. Inputs (metadata order): qs ks vs mask Wq bq Wk bk Wv bv Wo bo.
// d_out: out [B,S,D] (4.19M f32) followed by attn [B,H,S,S] (134.2M f32).
// ---------------------------------------------------------------------------
extern "C" void kernel_launch(void* const* d_in, const int* in_sizes, int n_in,
                              void* d_out, int out_size)
{
    const float* qs = (const float*)d_in[0];
    const float* ks = (const float*)d_in[1];
    const float* vs = (const float*)d_in[2];
    const void*  mask = d_in[3];
    const float* Wq = (const float*)d_in[4];
    const float* bq = (const float*)d_in[5];
    const float* Wk = (const float*)d_in[6];
    const float* bk = (const float*)d_in[7];
    const float* Wv = (const float*)d_in[8];
    const float* bv = (const float*)d_in[9];
    const float* Wo = (const float*)d_in[10];
    const float* bo = (const float*)d_in[11];

    float* out  = (float*)d_out;
    float* attn = out + (size_t)Bz * Sq * Dm;

    float *gq, *gk, *gv, *gctx;
    cudaGetSymbolAddress((void**)&gq, g_q);
    cudaGetSymbolAddress((void**)&gk, g_k);
    cudaGetSymbolAddress((void**)&gv, g_v);
    cudaGetSymbolAddress((void**)&gctx, g_ctx);

    const int M = Bz * Sq;   // 4096
    dim3 gProj(Dm / 128, M / 128);           // (8, 32)

    detect_mask_kernel<<<1, 256>>>((const unsigned char*)mask);

    sgemm128<<<gProj, 256>>>(qs, Wq, bq, gq, M, Dm, Dm, 1);
    sgemm128<<<gProj, 256>>>(ks, Wk, bk, gk, M, Dm, Dm, 1);
    sgemm128<<<gProj, 256>>>(vs, Wv, bv, gv, M, Dm, Dm, 1);

    scores_kernel<<<dim3(Sq / 128, Sq / 128, BH), 256>>>(mask, attn);

    softmax_kernel<<<(unsigned)((size_t)BH * Sq), 256>>>(attn);

    ctx_kernel<<<dim3(1, Sq / 128, BH), 256>>>(attn, gctx);

    sgemm128<<<gProj, 256>>>(gctx, Wo, bo, out, M, Dm, Dm, 0);
}

// round 2
// speedup vs baseline: 2.9063x; 2.9063x over previous
#include <cuda_runtime.h>
#include <cuda_bf16.h>
#include <math.h>
#include <stdint.h>

// Problem constants
#define Bz  2
#define Sq  2048
#define Dm  1024
#define Hn  16
#define DHd 64
#define BH  (Bz * Hn)   // 32

// ---------------------------------------------------------------------------
// Scratch (allocation-free __device__ globals)
// ---------------------------------------------------------------------------
__device__ float g_q[(size_t)BH * Sq * DHd];
__device__ float g_k[(size_t)BH * Sq * DHd];
__device__ float g_v[(size_t)BH * Sq * DHd];
__device__ float g_ctx[(size_t)Bz * Sq * Dm];
__device__ int   g_mask_is_int;

// ---------------------------------------------------------------------------
// Mask dtype detector (reads only first 4096 bytes; deterministic)
// ---------------------------------------------------------------------------
__global__ void detect_mask_kernel(const unsigned char* __restrict__ m) {
    __shared__ int any;
    if (threadIdx.x == 0) any = 0;
    __syncthreads();
    int local = 0;
    for (int i = threadIdx.x; i < Bz * Sq; i += blockDim.x)
        if ((i & 3) && m[i]) local = 1;
    if (local) atomicOr(&any, 1);
    __syncthreads();
    if (threadIdx.x == 0) g_mask_is_int = (any == 0) ? 1 : 0;
}

// ---------------------------------------------------------------------------
// MMA helpers
// ---------------------------------------------------------------------------
__device__ __forceinline__ uint32_t smem_u32(const void* p) {
    return (uint32_t)__cvta_generic_to_shared(p);
}
__device__ __forceinline__ void ldm4(uint32_t* r, uint32_t a) {
    asm volatile("ldmatrix.sync.aligned.m8n8.x4.shared.b16 {%0,%1,%2,%3},[%4];"
                 : "=r"(r[0]), "=r"(r[1]), "=r"(r[2]), "=r"(r[3]) : "r"(a));
}
__device__ __forceinline__ void ldm4t(uint32_t* r, uint32_t a) {
    asm volatile("ldmatrix.sync.aligned.m8n8.x4.trans.shared.b16 {%0,%1,%2,%3},[%4];"
                 : "=r"(r[0]), "=r"(r[1]), "=r"(r[2]), "=r"(r[3]) : "r"(a));
}
__device__ __forceinline__ void mma_bf16(float* c, const uint32_t* a, const uint32_t* b) {
    asm volatile(
        "mma.sync.aligned.m16n8k16.row.col.f32.bf16.bf16.f32 "
        "{%0,%1,%2,%3},{%4,%5,%6,%7},{%8,%9},{%0,%1,%2,%3};"
        : "+f"(c[0]), "+f"(c[1]), "+f"(c[2]), "+f"(c[3])
        : "r"(a[0]), "r"(a[1]), "r"(a[2]), "r"(a[3]), "r"(b[0]), "r"(b[1]));
}
__device__ __forceinline__ void split1(float x, __nv_bfloat16& h, __nv_bfloat16& l) {
    h = __float2bfloat16(x);
    l = __float2bfloat16(x - __bfloat162float(h));
}

// ---------------------------------------------------------------------------
// Fused bf16-split tensor-core GEMM.
// MODE 0: proj   C=A*W+bias, headsplit epilogue -> [BH,S,DH]     (M=4096,N=1024,K=1024)
// MODE 1: outproj C=A*W+bias, plain epilogue                     (M=4096,N=1024,K=1024)
// MODE 2: scores per-bh: Q*K^T * 0.125, mask -> -inf, to attn    (M=2048,N=2048,K=64)
// MODE 3: ctx    per-bh: P*V, remap to [B,S,D]                   (M=2048,N=64, K=2048)
// A is row-major [M][K]. B: MODE 0/1/3 row-major [K][N] (ldmatrix.trans);
// MODE 2 B is the K-matrix [N][K] (non-trans).
// fp32 inputs are split hi/lo bf16 at smem-fill; 3 MMA passes per tile.
// ---------------------------------------------------------------------------
template <int MODE>
__global__ void __launch_bounds__(256) mma_gemm(
    const float* __restrict__ A, const float* __restrict__ Bg,
    const float* __restrict__ bias, float* __restrict__ C,
    const void* __restrict__ mask)
{
    constexpr int BM = 128;
    constexpr int BN = (MODE == 3) ? 64 : 128;
    constexpr int BK = 32;
    constexpr int WN = BN / 4;       // 32 or 16
    constexpr int NT = WN / 8;       // 4 or 2
    constexpr int MT = 4;            // warp M tiles (64 rows)
    constexpr int SA = BK + 8;       // A smem row stride (bf16)
    constexpr bool BT = (MODE != 2); // B stored [k][n] (trans ldmatrix)
    constexpr int SB = BT ? (BN + 8) : (BK + 8);
    constexpr int BROWS = BT ? BK : BN;

    constexpr int Kdim = (MODE == 2) ? DHd : ((MODE == 3) ? Sq : Dm);
    constexpr int lda  = Kdim;
    constexpr int ldb  = (MODE == 2) ? DHd : ((MODE == 3) ? DHd : Dm);

    __shared__ __nv_bfloat16 Ah[BM * SA], Al[BM * SA];
    __shared__ __nv_bfloat16 Bh[BROWS * SB], Bl[BROWS * SB];

    const int z = blockIdx.z;
    if (MODE == 2) { A += (size_t)z * Sq * DHd; Bg += (size_t)z * Sq * DHd; }
    if (MODE == 3) { A += (size_t)z * Sq * Sq;  Bg += (size_t)z * Sq * DHd; }

    const int tid = threadIdx.x, lane = tid & 31, warp = tid >> 5;
    const int wm = (warp >> 2) * 64;
    const int wn = (warp & 3) * WN;
    const int bm = blockIdx.y * BM;
    const int bn = blockIdx.x * BN;

    float acc[MT][NT][4];
#pragma unroll
    for (int i = 0; i < MT; i++)
#pragma unroll
        for (int j = 0; j < NT; j++)
#pragma unroll
            for (int q = 0; q < 4; q++) acc[i][j][q] = 0.f;

    const uint32_t aH = smem_u32(Ah), aL = smem_u32(Al);
    const uint32_t bHb = smem_u32(Bh), bLb = smem_u32(Bl);

    for (int k0 = 0; k0 < Kdim; k0 += BK) {
        // ---- fill A (128 x 32 fp32 -> hi/lo bf16) ----
#pragma unroll
        for (int r = 0; r < 4; r++) {
            const int m  = (tid >> 3) + r * 32;
            const int kq = (tid & 7) * 4;
            float4 v = *(const float4*)(A + (size_t)(bm + m) * lda + k0 + kq);
            __nv_bfloat16 h0, h1, h2, h3, l0, l1, l2, l3;
            split1(v.x, h0, l0); split1(v.y, h1, l1);
            split1(v.z, h2, l2); split1(v.w, h3, l3);
            *(__nv_bfloat162*)&Ah[m * SA + kq]     = __nv_bfloat162{h0, h1};
            *(__nv_bfloat162*)&Ah[m * SA + kq + 2] = __nv_bfloat162{h2, h3};
            *(__nv_bfloat162*)&Al[m * SA + kq]     = __nv_bfloat162{l0, l1};
            *(__nv_bfloat162*)&Al[m * SA + kq + 2] = __nv_bfloat162{l2, l3};
        }
        // ---- fill B ----
        if (BT) {
            constexpr int NV  = BN / 4;         // float4 per k-row
            constexpr int RPP = 256 / NV;       // k-rows per pass
#pragma unroll
            for (int r = 0; r < BK / RPP; r++) {
                const int kr = (tid / NV) + r * RPP;
                const int n4 = (tid % NV) * 4;
                float4 v = *(const float4*)(Bg + (size_t)(k0 + kr) * ldb + bn + n4);
                __nv_bfloat16 h0, h1, h2, h3, l0, l1, l2, l3;
                split1(v.x, h0, l0); split1(v.y, h1, l1);
                split1(v.z, h2, l2); split1(v.w, h3, l3);
                *(__nv_bfloat162*)&Bh[kr * SB + n4]     = __nv_bfloat162{h0, h1};
                *(__nv_bfloat162*)&Bh[kr * SB + n4 + 2] = __nv_bfloat162{h2, h3};
                *(__nv_bfloat162*)&Bl[kr * SB + n4]     = __nv_bfloat162{l0, l1};
                *(__nv_bfloat162*)&Bl[kr * SB + n4 + 2] = __nv_bfloat162{l2, l3};
            }
        } else {
#pragma unroll
            for (int r = 0; r < 4; r++) {
                const int n  = (tid >> 3) + r * 32;
                const int kq = (tid & 7) * 4;
                float4 v = *(const float4*)(Bg + (size_t)(bn + n) * ldb + k0 + kq);
                __nv_bfloat16 h0, h1, h2, h3, l0, l1, l2, l3;
                split1(v.x, h0, l0); split1(v.y, h1, l1);
                split1(v.z, h2, l2); split1(v.w, h3, l3);
                *(__nv_bfloat162*)&Bh[n * SB + kq]     = __nv_bfloat162{h0, h1};
                *(__nv_bfloat162*)&Bh[n * SB + kq + 2] = __nv_bfloat162{h2, h3};
                *(__nv_bfloat162*)&Bl[n * SB + kq]     = __nv_bfloat162{l0, l1};
                *(__nv_bfloat162*)&Bl[n * SB + kq + 2] = __nv_bfloat162{l2, l3};
            }
        }
        __syncthreads();

#pragma unroll
        for (int kk = 0; kk < BK; kk += 16) {
            // A fragments (hi & lo)
            uint32_t ah[MT][4], al[MT][4];
            const int arow = wm + (lane & 7) + ((lane >> 3) & 1) * 8;
            const int acol = kk + (lane >> 4) * 8;
#pragma unroll
            for (int mt = 0; mt < MT; mt++) {
                const uint32_t off = (uint32_t)(((arow + mt * 16) * SA + acol) * 2);
                ldm4(ah[mt], aH + off);
                ldm4(al[mt], aL + off);
            }
            // B fragments (hi & lo)
            uint32_t bh[NT][2], bl[NT][2];
            if (BT) {
                const int brow = kk + (lane & 7) + ((lane >> 3) & 1) * 8;
#pragma unroll
                for (int sp = 0; sp < NT / 2; sp++) {
                    const int bcol = wn + sp * 16 + (lane >> 4) * 8;
                    const uint32_t off = (uint32_t)((brow * SB + bcol) * 2);
                    uint32_t t[4];
                    ldm4t(t, bHb + off);
                    bh[2 * sp][0] = t[0]; bh[2 * sp][1] = t[1];
                    bh[2 * sp + 1][0] = t[2]; bh[2 * sp + 1][1] = t[3];
                    ldm4t(t, bLb + off);
                    bl[2 * sp][0] = t[0]; bl[2 * sp][1] = t[1];
                    bl[2 * sp + 1][0] = t[2]; bl[2 * sp + 1][1] = t[3];
                }
            } else {
#pragma unroll
                for (int sp = 0; sp < NT / 2; sp++) {
                    const int brow = wn + sp * 16 + (lane & 7) + ((lane >> 3) & 1) * 8;
                    const int bcol = kk + (lane >> 4) * 8;
                    const uint32_t off = (uint32_t)((brow * SB + bcol) * 2);
                    uint32_t t[4];
                    ldm4(t, bHb + off);
                    bh[2 * sp][0] = t[0]; bh[2 * sp + 1][0] = t[1];
                    bh[2 * sp][1] = t[2]; bh[2 * sp + 1][1] = t[3];
                    ldm4(t, bLb + off);
                    bl[2 * sp][0] = t[0]; bl[2 * sp + 1][0] = t[1];
                    bl[2 * sp][1] = t[2]; bl[2 * sp + 1][1] = t[3];
                }
            }
            // 3-pass split MMA: hi*hi + hi*lo + lo*hi
#pragma unroll
            for (int mt = 0; mt < MT; mt++)
#pragma unroll
                for (int nt = 0; nt < NT; nt++) {
                    mma_bf16(acc[mt][nt], ah[mt], bh[nt]);
                    mma_bf16(acc[mt][nt], ah[mt], bl[nt]);
                    mma_bf16(acc[mt][nt], al[mt], bh[nt]);
                }
        }
        __syncthreads();
    }

    // ---- epilogue ----
    const int g  = lane >> 2;
    const int t2 = (lane & 3) * 2;
    const float NEG_INF = __int_as_float(0xff800000);
    const int mint = (MODE == 2) ? g_mask_is_int : 0;
    const int zb = z / Hn, zh = z % Hn;

#pragma unroll
    for (int mt = 0; mt < MT; mt++) {
#pragma unroll
        for (int nt = 0; nt < NT; nt++) {
            const int col = bn + wn + nt * 8 + t2;
#pragma unroll
            for (int h2 = 0; h2 < 2; h2++) {
                const int row = bm + wm + mt * 16 + g + h2 * 8;
                float c0 = acc[mt][nt][h2 * 2 + 0];
                float c1 = acc[mt][nt][h2 * 2 + 1];
                if (MODE == 0) {
                    c0 += bias[col]; c1 += bias[col + 1];
                    const int bb = row >> 11, ss = row & (Sq - 1);
                    const int hh = col >> 6,  dh = col & (DHd - 1);
                    float* dst = C + (((size_t)(bb * Hn + hh)) * Sq + ss) * DHd + dh;
                    *(float2*)dst = make_float2(c0, c1);
                } else if (MODE == 1) {
                    c0 += bias[col]; c1 += bias[col + 1];
                    *(float2*)(C + (size_t)row * Dm + col) = make_float2(c0, c1);
                } else if (MODE == 2) {
                    bool m0, m1;
                    if (mint) {
                        m0 = ((const int*)mask)[zb * Sq + col] != 0;
                        m1 = ((const int*)mask)[zb * Sq + col + 1] != 0;
                    } else {
                        m0 = ((const unsigned char*)mask)[zb * Sq + col] != 0;
                        m1 = ((const unsigned char*)mask)[zb * Sq + col + 1] != 0;
                    }
                    float2 v = make_float2(m0 ? c0 * 0.125f : NEG_INF,
                                           m1 ? c1 * 0.125f : NEG_INF);
                    *(float2*)(C + ((size_t)z * Sq + row) * Sq + col) = v;
                } else { // MODE 3
                    float* dst = C + ((size_t)zb * Sq + row) * Dm + zh * DHd + col;
                    *(float2*)dst = make_float2(c0, c1);
                }
            }
        }
    }
}

// ---------------------------------------------------------------------------
// In-place row softmax over S=2048 (unchanged from passing baseline)
// ---------------------------------------------------------------------------
__global__ void __launch_bounds__(256) softmax_kernel(float* __restrict__ attn)
{
    const size_t row = blockIdx.x;
    float4* p = (float4*)(attn + row * Sq);
    const int tid = threadIdx.x;

    float4 v0 = p[tid];
    float4 v1 = p[tid + 256];

    float m = fmaxf(fmaxf(fmaxf(v0.x, v0.y), fmaxf(v0.z, v0.w)),
                    fmaxf(fmaxf(v1.x, v1.y), fmaxf(v1.z, v1.w)));
#pragma unroll
    for (int o = 16; o; o >>= 1) m = fmaxf(m, __shfl_xor_sync(~0u, m, o));

    __shared__ float sred[8];
    if ((tid & 31) == 0) sred[tid >> 5] = m;
    __syncthreads();
    if (tid < 32) {
        float t = (tid < 8) ? sred[tid] : __int_as_float(0xff800000);
#pragma unroll
        for (int o = 4; o; o >>= 1) t = fmaxf(t, __shfl_xor_sync(~0u, t, o));
        if (tid == 0) sred[0] = t;
    }
    __syncthreads();
    m = sred[0];
    __syncthreads();

    float e[8];
    e[0] = expf(v0.x - m); e[1] = expf(v0.y - m);
    e[2] = expf(v0.z - m); e[3] = expf(v0.w - m);
    e[4] = expf(v1.x - m); e[5] = expf(v1.y - m);
    e[6] = expf(v1.z - m); e[7] = expf(v1.w - m);
    float s = e[0] + e[1] + e[2] + e[3] + e[4] + e[5] + e[6] + e[7];
#pragma unroll
    for (int o = 16; o; o >>= 1) s += __shfl_xor_sync(~0u, s, o);
    if ((tid & 31) == 0) sred[tid >> 5] = s;
    __syncthreads();
    if (tid < 32) {
        float t = (tid < 8) ? sred[tid] : 0.f;
#pragma unroll
        for (int o = 4; o; o >>= 1) t += __shfl_xor_sync(~0u, t, o);
        if (tid == 0) sred[0] = t;
    }
    __syncthreads();
    const float inv = 1.f / sred[0];

    v0 = make_float4(e[0] * inv, e[1] * inv, e[2] * inv, e[3] * inv);
    v1 = make_float4(e[4] * inv, e[5] * inv, e[6] * inv, e[7] * inv);
    p[tid]       = v0;
    p[tid + 256] = v1;
}

// ---------------------------------------------------------------------------
// Launch. Inputs: qs ks vs mask Wq bq Wk bk Wv bv Wo bo.
// d_out: out [B,S,D] then attn [B,H,S,S].
// ---------------------------------------------------------------------------
extern "C" void kernel_launch(void* const* d_in, const int* in_sizes, int n_in,
                              void* d_out, int out_size)
{
    const float* qs = (const float*)d_in[0];
    const float* ks = (const float*)d_in[1];
    const float* vs = (const float*)d_in[2];
    const void*  mask = d_in[3];
    const float* Wq = (const float*)d_in[4];
    const float* bq = (const float*)d_in[5];
    const float* Wk = (const float*)d_in[6];
    const float* bk = (const float*)d_in[7];
    const float* Wv = (const float*)d_in[8];
    const float* bv = (const float*)d_in[9];
    const float* Wo = (const float*)d_in[10];
    const float* bo = (const float*)d_in[11];

    float* out  = (float*)d_out;
    float* attn = out + (size_t)Bz * Sq * Dm;

    float *gq, *gk, *gv, *gctx;
    cudaGetSymbolAddress((void**)&gq, g_q);
    cudaGetSymbolAddress((void**)&gk, g_k);
    cudaGetSymbolAddress((void**)&gv, g_v);
    cudaGetSymbolAddress((void**)&gctx, g_ctx);

    detect_mask_kernel<<<1, 256>>>((const unsigned char*)mask);

    dim3 gProj(Dm / 128, (Bz * Sq) / 128);            // (8, 32)
    mma_gemm<0><<<gProj, 256>>>(qs, Wq, bq, gq, nullptr);
    mma_gemm<0><<<gProj, 256>>>(ks, Wk, bk, gk, nullptr);
    mma_gemm<0><<<gProj, 256>>>(vs, Wv, bv, gv, nullptr);

    mma_gemm<2><<<dim3(Sq / 128, Sq / 128, BH), 256>>>(gq, gk, nullptr, attn, mask);

    softmax_kernel<<<(unsigned)((size_t)BH * Sq), 256>>>(attn);

    mma_gemm<3><<<dim3(1, Sq / 128, BH), 256>>>(attn, gv, nullptr, gctx, nullptr);

    mma_gemm<1><<<gProj, 256>>>(gctx, Wo, bo, out, nullptr);
}